// round 1
// baseline (speedup 1.0000x reference)
#include <cuda_runtime.h>
#include <cstdint>

// ---------------- problem constants ----------------
constexpr int S = 1024, B = 8, D = 1024, H = 16, F = 4096, E = 8;
constexpr int HD = D / H;           // 64
constexpr int N = S * B;            // 8192
constexpr int CAP = 4 * N / E;      // 4096

// ---------------- scratch (device globals; no allocations) ----------------
__device__ float g_xn [N * D];
__device__ float g_q  [N * D];
__device__ float g_k  [N * D];
__device__ float g_v  [N * D];
__device__ float g_ao [N * D];
__device__ float g_x1 [N * D];
__device__ float g_tok[N * D];
__device__ float g_disp[E * CAP * D];       // 128 MB
__device__ float g_h   [E * CAP * F];       // 512 MB
__device__ float g_eo  [E * CAP * D];       // 128 MB
__device__ float g_gates[N * E];
__device__ int   g_eidx[N];
__device__ float g_gp  [N];
__device__ int   g_slot[N];
__device__ float g_gv  [N];
__device__ int   g_cnt [E];

// ---------------- LayerNorm ----------------
__global__ void __launch_bounds__(256) ln_kernel(const float* __restrict__ x,
                                                 const float* __restrict__ gam,
                                                 const float* __restrict__ bet,
                                                 float* __restrict__ y) {
    int n = blockIdx.x;
    const float* row = x + (long)n * D;
    int t = threadIdx.x;
    float s = 0.f, s2 = 0.f;
    for (int d = t; d < D; d += 256) { float v = row[d]; s += v; s2 += v * v; }
    // block reduce (deterministic tree)
    __shared__ float r1[256], r2[256];
    r1[t] = s; r2[t] = s2; __syncthreads();
    for (int st = 128; st > 0; st >>= 1) {
        if (t < st) { r1[t] += r1[t + st]; r2[t] += r2[t + st]; }
        __syncthreads();
    }
    float mean = r1[0] / D;
    float var  = r2[0] / D - mean * mean;
    float inv  = rsqrtf(var + 1e-5f);
    float* yo = y + (long)n * D;
    for (int d = t; d < D; d += 256)
        yo[d] = (row[d] - mean) * inv * gam[d] + bet[d];
}

// ---------------- generic tiled SGEMM ----------------
// C[M,Nc] = (A[M,K] @ Bm[K,Nc] + bias) * scale (+ resid) (relu optional)
// batched over blockIdx.z with element strides.
__global__ void __launch_bounds__(256) gemm_kernel(
    const float* __restrict__ A, const float* __restrict__ Bm,
    const float* __restrict__ bias, const float* __restrict__ resid,
    float* __restrict__ C,
    int M, int Nc, int K, float scale, int relu,
    long long sA, long long sB, long long sBias, long long sC)
{
    int bz = blockIdx.z;
    A    += (long long)bz * sA;
    Bm   += (long long)bz * sB;
    bias += (long long)bz * sBias;
    C    += (long long)bz * sC;
    if (resid) resid += (long long)bz * sC;

    __shared__ float As[16][128];
    __shared__ float Bs[16][128];
    int t  = threadIdx.x;
    int tx = t & 15, ty = t >> 4;
    int m0 = blockIdx.y * 128, n0 = blockIdx.x * 128;

    float acc[8][8];
#pragma unroll
    for (int i = 0; i < 8; i++)
#pragma unroll
        for (int j = 0; j < 8; j++) acc[i][j] = 0.f;

    for (int k0 = 0; k0 < K; k0 += 16) {
#pragma unroll
        for (int l = 0; l < 2; l++) {
            int f  = t + l * 256;
            int r  = f >> 2;
            int c4 = (f & 3) * 4;
            float4 v = *(const float4*)(A + (long long)(m0 + r) * K + k0 + c4);
            As[c4 + 0][r] = v.x; As[c4 + 1][r] = v.y;
            As[c4 + 2][r] = v.z; As[c4 + 3][r] = v.w;
        }
#pragma unroll
        for (int l = 0; l < 2; l++) {
            int f  = t + l * 256;
            int r  = f >> 5;
            int c4 = (f & 31) * 4;
            *(float4*)(&Bs[r][c4]) = *(const float4*)(Bm + (long long)(k0 + r) * Nc + n0 + c4);
        }
        __syncthreads();
#pragma unroll
        for (int kk = 0; kk < 16; kk++) {
            float a[8], b[8];
#pragma unroll
            for (int i = 0; i < 8; i++) a[i] = As[kk][ty * 8 + i];
#pragma unroll
            for (int j = 0; j < 8; j++) b[j] = Bs[kk][tx * 8 + j];
#pragma unroll
            for (int i = 0; i < 8; i++)
#pragma unroll
                for (int j = 0; j < 8; j++) acc[i][j] += a[i] * b[j];
        }
        __syncthreads();
    }
#pragma unroll
    for (int i = 0; i < 8; i++) {
        int row = m0 + ty * 8 + i;
#pragma unroll
        for (int j = 0; j < 8; j++) {
            int col = n0 + tx * 8 + j;
            float v = (acc[i][j] + bias[col]) * scale;
            if (resid) v += resid[(long long)row * Nc + col];
            if (relu)  v = fmaxf(v, 0.f);
            C[(long long)row * Nc + col] = v;
        }
    }
}

// ---------------- flash attention (fp32, causal) ----------------
// grid (S/128, B*H), 128 threads; each thread owns one query row.
constexpr int QT = 128, KT = 64;
constexpr int ATTN_SMEM = (QT * (HD + 1) + 2 * KT * HD) * 4;  // 66048 B

__global__ void __launch_bounds__(128) attn_kernel(
    const float* __restrict__ Q, const float* __restrict__ Kg,
    const float* __restrict__ Vg, float* __restrict__ O)
{
    extern __shared__ float sm[];
    float* q_s = sm;                       // [QT][HD+1]
    float* k_s = sm + QT * (HD + 1);       // [KT][HD]
    float* v_s = k_s + KT * HD;            // [KT][HD]

    int bh = blockIdx.y;
    int h  = bh % H, b = bh / H;
    int q0 = blockIdx.x * QT;
    int t  = threadIdx.x;
    long base = (long)b * D + (long)h * HD;

    // load Q tile (padded stride HD+1 for conflict-free reads)
    for (int f = t; f < QT * HD / 4; f += 128) {
        int r  = f / (HD / 4);
        int c4 = (f % (HD / 4)) * 4;
        float4 v = *(const float4*)(Q + (long)(q0 + r) * (B * D) + base + c4);
        q_s[r * (HD + 1) + c4 + 0] = v.x;
        q_s[r * (HD + 1) + c4 + 1] = v.y;
        q_s[r * (HD + 1) + c4 + 2] = v.z;
        q_s[r * (HD + 1) + c4 + 3] = v.w;
    }
    __syncthreads();

    int sq = q0 + t;
    float m_run = -1e30f, l_run = 0.f;
    float acc[HD];
#pragma unroll
    for (int d = 0; d < HD; d++) acc[d] = 0.f;

    int kend = q0 + QT;  // causal: no key tile beyond query block end
    for (int k0 = 0; k0 < kend; k0 += KT) {
        for (int f = t; f < KT * HD / 4; f += 128) {
            int r  = f / (HD / 4);
            int c4 = (f % (HD / 4)) * 4;
            *(float4*)(&k_s[r * HD + c4]) =
                *(const float4*)(Kg + (long)(k0 + r) * (B * D) + base + c4);
            *(float4*)(&v_s[r * HD + c4]) =
                *(const float4*)(Vg + (long)(k0 + r) * (B * D) + base + c4);
        }
        __syncthreads();

        float s[KT];
#pragma unroll
        for (int j = 0; j < KT; j++) s[j] = 0.f;
        for (int d = 0; d < HD; d++) {
            float qd = q_s[t * (HD + 1) + d];
#pragma unroll
            for (int j = 0; j < KT; j++) s[j] += qd * k_s[j * HD + d];
        }
        float mnew = m_run;
#pragma unroll
        for (int j = 0; j < KT; j++) {
            if (k0 + j > sq) s[j] = -1e9f;       // causal mask (== adding -1e9)
            mnew = fmaxf(mnew, s[j]);
        }
        float corr = __expf(m_run - mnew);
        l_run *= corr;
#pragma unroll
        for (int d = 0; d < HD; d++) acc[d] *= corr;
        for (int j = 0; j < KT; j++) {
            float p = __expf(s[j] - mnew);
            l_run += p;
#pragma unroll
            for (int d = 0; d < HD; d++) acc[d] += p * v_s[j * HD + d];
        }
        m_run = mnew;
        __syncthreads();
    }
    float inv = 1.f / l_run;
    float* op = O + (long)sq * (B * D) + base;
#pragma unroll
    for (int c4 = 0; c4 < HD; c4 += 4) {
        float4 v;
        v.x = acc[c4 + 0] * inv; v.y = acc[c4 + 1] * inv;
        v.z = acc[c4 + 2] * inv; v.w = acc[c4 + 3] * inv;
        *(float4*)(op + c4) = v;
    }
}

// ---------------- gate: logits, softmax, argmax ----------------
__global__ void __launch_bounds__(256) gate_kernel(
    const float* __restrict__ tok, const float* __restrict__ gw,
    float* __restrict__ gates, int* __restrict__ eidx, float* __restrict__ gp)
{
    int n = blockIdx.x, t = threadIdx.x;
    const float* row = tok + (long)n * D;
    float p[E];
#pragma unroll
    for (int e = 0; e < E; e++) p[e] = 0.f;
    for (int d = t; d < D; d += 256) {
        float xv = row[d];
        const float* w = gw + (long)d * E;
#pragma unroll
        for (int e = 0; e < E; e++) p[e] += xv * w[e];
    }
    __shared__ float red[256 * E];
#pragma unroll
    for (int e = 0; e < E; e++) red[t * E + e] = p[e];
    __syncthreads();
    for (int st = 128; st > 0; st >>= 1) {
        if (t < st)
#pragma unroll
            for (int e = 0; e < E; e++) red[t * E + e] += red[(t + st) * E + e];
        __syncthreads();
    }
    if (t == 0) {
        float lg[E], mx = -1e30f;
#pragma unroll
        for (int e = 0; e < E; e++) { lg[e] = red[e]; mx = fmaxf(mx, lg[e]); }
        float sum = 0.f, pr[E];
#pragma unroll
        for (int e = 0; e < E; e++) { pr[e] = __expf(lg[e] - mx); sum += pr[e]; }
        float inv = 1.f / sum;
        int best = 0; float bv = -1e30f;
#pragma unroll
        for (int e = 0; e < E; e++) {
            float g = pr[e] * inv;
            gates[(long)n * E + e] = g;
            if (g > bv) { bv = g; best = e; }   // first-max rule
        }
        eidx[n] = best;
        gp[n]   = bv;
    }
}

// ---------------- routing scan (deterministic, single block) ----------------
__global__ void __launch_bounds__(256) scan_kernel(
    const int* __restrict__ eidx, const float* __restrict__ gp,
    int* __restrict__ slot, float* __restrict__ gv, int* __restrict__ cnt)
{
    __shared__ int scnt[256][E];
    int t = threadIdx.x;
    int c[E];
#pragma unroll
    for (int e = 0; e < E; e++) c[e] = 0;
    int n0 = t * (N / 256);
    for (int i = 0; i < N / 256; i++) c[eidx[n0 + i]]++;
#pragma unroll
    for (int e = 0; e < E; e++) scnt[t][e] = c[e];
    __syncthreads();
    if (t < E) {
        int run = 0;
        for (int j = 0; j < 256; j++) { int tmp = scnt[j][t]; scnt[j][t] = run; run += tmp; }
        cnt[t] = run;
    }
    __syncthreads();
    int off[E];
#pragma unroll
    for (int e = 0; e < E; e++) off[e] = scnt[t][e];
    for (int i = 0; i < N / 256; i++) {
        int n = n0 + i;
        int e = eidx[n];
        int l = off[e]++;
        bool keep = (l < CAP);
        slot[n] = keep ? e * CAP + l : -1;
        gv[n]   = keep ? gp[n] : 0.f;
    }
}

// ---------------- l_aux (deterministic tree reduce) ----------------
__global__ void __launch_bounds__(256) laux_kernel(
    const float* __restrict__ gates, const int* __restrict__ cnt,
    float* __restrict__ out_laux)
{
    __shared__ float red[256];
    int t = threadIdx.x;
    float loc[E];
#pragma unroll
    for (int e = 0; e < E; e++) loc[e] = 0.f;
    for (int n = t; n < N; n += 256)
#pragma unroll
        for (int e = 0; e < E; e++) loc[e] += gates[(long)n * E + e];
    float total[E];
    for (int e = 0; e < E; e++) {
        red[t] = loc[e]; __syncthreads();
        for (int st = 128; st > 0; st >>= 1) {
            if (t < st) red[t] += red[t + st];
            __syncthreads();
        }
        if (t == 0) total[e] = red[0];
        __syncthreads();
    }
    if (t == 0) {
        float la = 0.f;
        for (int e = 0; e < E; e++)
            la += (total[e] / N) * ((float)cnt[e] / N);
        *out_laux = (float)E * la;
    }
}

// ---------------- dispatch / combine ----------------
__global__ void __launch_bounds__(256) dispatch_kernel(
    const float* __restrict__ tok, const int* __restrict__ slot,
    float* __restrict__ disp)
{
    int n = blockIdx.x;
    int s = slot[n];
    if (s < 0) return;
    const float4* src = (const float4*)(tok + (long)n * D);
    float4* dst = (float4*)(disp + (long)s * D);
    dst[threadIdx.x] = src[threadIdx.x];
}

__global__ void __launch_bounds__(256) combine_kernel(
    const float* __restrict__ x1, const float* __restrict__ eo,
    const int* __restrict__ slot, const float* __restrict__ gv,
    float* __restrict__ out)
{
    int n = blockIdx.x, t = threadIdx.x;
    int s = slot[n];
    float g = gv[n];
    float4 r = ((const float4*)(x1 + (long)n * D))[t];
    if (s >= 0) {
        float4 v = ((const float4*)(eo + (long)s * D))[t];
        r.x += v.x * g; r.y += v.y * g; r.z += v.z * g; r.w += v.w * g;
    }
    ((float4*)(out + (long)n * D))[t] = r;
}

// ---------------- launch ----------------
extern "C" void kernel_launch(void* const* d_in, const int* in_sizes, int n_in,
                              void* d_out, int out_size) {
    const float* x    = (const float*)d_in[0];
    const float* wq   = (const float*)d_in[2];
    const float* bq   = (const float*)d_in[3];
    const float* wk   = (const float*)d_in[4];
    const float* bk   = (const float*)d_in[5];
    const float* wv   = (const float*)d_in[6];
    const float* bv   = (const float*)d_in[7];
    const float* wo   = (const float*)d_in[8];
    const float* bo   = (const float*)d_in[9];
    const float* ln1g = (const float*)d_in[10];
    const float* ln1b = (const float*)d_in[11];
    const float* ln2g = (const float*)d_in[12];
    const float* ln2b = (const float*)d_in[13];
    const float* gw   = (const float*)d_in[14];
    const float* w1   = (const float*)d_in[15];
    const float* b1   = (const float*)d_in[16];
    const float* w2   = (const float*)d_in[17];
    const float* b2   = (const float*)d_in[18];
    float* out = (float*)d_out;

    float *xn, *q, *k, *v, *ao, *x1, *tok, *disp, *hbuf, *eo, *gates, *gp, *gv;
    int *eidx, *slot, *cnt;
    cudaGetSymbolAddress((void**)&xn,   g_xn);
    cudaGetSymbolAddress((void**)&q,    g_q);
    cudaGetSymbolAddress((void**)&k,    g_k);
    cudaGetSymbolAddress((void**)&v,    g_v);
    cudaGetSymbolAddress((void**)&ao,   g_ao);
    cudaGetSymbolAddress((void**)&x1,   g_x1);
    cudaGetSymbolAddress((void**)&tok,  g_tok);
    cudaGetSymbolAddress((void**)&disp, g_disp);
    cudaGetSymbolAddress((void**)&hbuf, g_h);
    cudaGetSymbolAddress((void**)&eo,   g_eo);
    cudaGetSymbolAddress((void**)&gates,g_gates);
    cudaGetSymbolAddress((void**)&gp,   g_gp);
    cudaGetSymbolAddress((void**)&gv,   g_gv);
    cudaGetSymbolAddress((void**)&eidx, g_eidx);
    cudaGetSymbolAddress((void**)&slot, g_slot);
    cudaGetSymbolAddress((void**)&cnt,  g_cnt);

    cudaFuncSetAttribute(attn_kernel,
                         cudaFuncAttributeMaxDynamicSharedMemorySize, ATTN_SMEM);

    const float qscale = 0.125f;  // HD^-0.5

    // 1) LN1
    ln_kernel<<<N, 256>>>(x, ln1g, ln1b, xn);
    // 2) Q/K/V projections
    gemm_kernel<<<dim3(D / 128, N / 128, 1), 256>>>(xn, wq, bq, nullptr, q,
        N, D, D, qscale, 0, 0, 0, 0, 0);
    gemm_kernel<<<dim3(D / 128, N / 128, 1), 256>>>(xn, wk, bk, nullptr, k,
        N, D, D, 1.f, 0, 0, 0, 0, 0);
    gemm_kernel<<<dim3(D / 128, N / 128, 1), 256>>>(xn, wv, bv, nullptr, v,
        N, D, D, 1.f, 0, 0, 0, 0, 0);
    // 3) attention
    attn_kernel<<<dim3(S / QT, B * H), 128, ATTN_SMEM>>>(q, k, v, ao);
    // 4) output projection + residual
    gemm_kernel<<<dim3(D / 128, N / 128, 1), 256>>>(ao, wo, bo, x, x1,
        N, D, D, 1.f, 0, 0, 0, 0, 0);
    // 5) LN2
    ln_kernel<<<N, 256>>>(x1, ln2g, ln2b, tok);
    // 6) gate
    gate_kernel<<<N, 256>>>(tok, gw, gates, eidx, gp);
    // 7) routing scan
    scan_kernel<<<1, 256>>>(eidx, gp, slot, gv, cnt);
    // 8) l_aux -> last output element
    laux_kernel<<<1, 256>>>(gates, cnt, out + (out_size - 1));
    // 9) dispatch
    dispatch_kernel<<<N, 256>>>(tok, slot, disp);
    // 10) expert GEMM1 (relu)
    gemm_kernel<<<dim3(F / 128, CAP / 128, E), 256>>>(disp, w1, b1, nullptr, hbuf,
        CAP, F, D, 1.f, 1,
        (long long)CAP * D, (long long)D * F, (long long)F, (long long)CAP * F);
    // 11) expert GEMM2
    gemm_kernel<<<dim3(D / 128, CAP / 128, E), 256>>>(hbuf, w2, b2, nullptr, eo,
        CAP, D, F, 1.f, 0,
        (long long)CAP * F, (long long)F * D, (long long)D, (long long)CAP * D);
    // 12) combine + residual -> output
    combine_kernel<<<N, 256>>>(x1, eo, slot, gv, out);
}

// round 2
// speedup vs baseline: 1.9447x; 1.9447x over previous
#include <cuda_runtime.h>
#include <cstdint>

// ---------------- problem constants ----------------
constexpr int S = 1024, B = 8, D = 1024, H = 16, F = 4096, E = 8;
constexpr int HD = D / H;           // 64
constexpr int N = S * B;            // 8192
constexpr int CAP = 4 * N / E;      // 4096

// ---------------- scratch (device globals; no allocations) ----------------
__device__ float g_xn [N * D];
__device__ float g_q  [N * D];
__device__ float g_k  [N * D];
__device__ float g_v  [N * D];
__device__ float g_ao [N * D];
__device__ float g_x1 [N * D];
__device__ float g_tok[N * D];
__device__ float g_disp[E * CAP * D];       // 128 MB
__device__ float g_h   [E * CAP * F];       // 512 MB
__device__ float g_eo  [E * CAP * D];       // 128 MB
__device__ float g_gates[N * E];
__device__ int   g_eidx[N];
__device__ float g_gp  [N];
__device__ int   g_slot[N];
__device__ float g_gv  [N];
__device__ int   g_cnt [E];

// ---------------- LayerNorm ----------------
__global__ void __launch_bounds__(256) ln_kernel(const float* __restrict__ x,
                                                 const float* __restrict__ gam,
                                                 const float* __restrict__ bet,
                                                 float* __restrict__ y) {
    int n = blockIdx.x;
    const float* row = x + (long)n * D;
    int t = threadIdx.x;
    float s = 0.f, s2 = 0.f;
    for (int d = t; d < D; d += 256) { float v = row[d]; s += v; s2 += v * v; }
    __shared__ float r1[256], r2[256];
    r1[t] = s; r2[t] = s2; __syncthreads();
    for (int st = 128; st > 0; st >>= 1) {
        if (t < st) { r1[t] += r1[t + st]; r2[t] += r2[t + st]; }
        __syncthreads();
    }
    float mean = r1[0] / D;
    float var  = r2[0] / D - mean * mean;
    float inv  = rsqrtf(var + 1e-5f);
    float* yo = y + (long)n * D;
    for (int d = t; d < D; d += 256)
        yo[d] = (row[d] - mean) * inv * gam[d] + bet[d];
}

// ---------------- fp32 tiled SGEMM (used upstream of the gate) ----------------
__global__ void __launch_bounds__(256) gemm_kernel(
    const float* __restrict__ A, const float* __restrict__ Bm,
    const float* __restrict__ bias, const float* __restrict__ resid,
    float* __restrict__ C,
    int M, int Nc, int K, float scale, int relu,
    long long sA, long long sB, long long sBias, long long sC)
{
    int bz = blockIdx.z;
    A    += (long long)bz * sA;
    Bm   += (long long)bz * sB;
    bias += (long long)bz * sBias;
    C    += (long long)bz * sC;
    if (resid) resid += (long long)bz * sC;

    __shared__ float As[16][128];
    __shared__ float Bs[16][128];
    int t  = threadIdx.x;
    int tx = t & 15, ty = t >> 4;
    int m0 = blockIdx.y * 128, n0 = blockIdx.x * 128;

    float acc[8][8];
#pragma unroll
    for (int i = 0; i < 8; i++)
#pragma unroll
        for (int j = 0; j < 8; j++) acc[i][j] = 0.f;

    for (int k0 = 0; k0 < K; k0 += 16) {
#pragma unroll
        for (int l = 0; l < 2; l++) {
            int f  = t + l * 256;
            int r  = f >> 2;
            int c4 = (f & 3) * 4;
            float4 v = *(const float4*)(A + (long long)(m0 + r) * K + k0 + c4);
            As[c4 + 0][r] = v.x; As[c4 + 1][r] = v.y;
            As[c4 + 2][r] = v.z; As[c4 + 3][r] = v.w;
        }
#pragma unroll
        for (int l = 0; l < 2; l++) {
            int f  = t + l * 256;
            int r  = f >> 5;
            int c4 = (f & 31) * 4;
            *(float4*)(&Bs[r][c4]) = *(const float4*)(Bm + (long long)(k0 + r) * Nc + n0 + c4);
        }
        __syncthreads();
#pragma unroll
        for (int kk = 0; kk < 16; kk++) {
            float a[8], b[8];
#pragma unroll
            for (int i = 0; i < 8; i++) a[i] = As[kk][ty * 8 + i];
#pragma unroll
            for (int j = 0; j < 8; j++) b[j] = Bs[kk][tx * 8 + j];
#pragma unroll
            for (int i = 0; i < 8; i++)
#pragma unroll
                for (int j = 0; j < 8; j++) acc[i][j] += a[i] * b[j];
        }
        __syncthreads();
    }
#pragma unroll
    for (int i = 0; i < 8; i++) {
        int row = m0 + ty * 8 + i;
#pragma unroll
        for (int j = 0; j < 8; j++) {
            int col = n0 + tx * 8 + j;
            float v = (acc[i][j] + bias[col]) * scale;
            if (resid) v += resid[(long long)row * Nc + col];
            if (relu)  v = fmaxf(v, 0.f);
            C[(long long)row * Nc + col] = v;
        }
    }
}

// ---------------- tf32 tensor-core GEMM (expert FFN, downstream of routing) ----
__device__ __forceinline__ uint32_t f2tf32(float f) {
    uint32_t u;
    asm("cvt.rna.tf32.f32 %0, %1;" : "=r"(u) : "f"(f));
    return u;
}

// C[M,Nc] = op(A[M,K] @ Bm[K,Nc] + bias), batched over blockIdx.z.
// Block tile 128x128, 8 warps, warp tile 64x32, mma.sync m16n8k8 tf32.
template<int RELU>
__global__ void __launch_bounds__(256) gemm_tf32_kernel(
    const float* __restrict__ A, const float* __restrict__ Bm,
    const float* __restrict__ bias, float* __restrict__ C,
    int M, int Nc, int K,
    long long sA, long long sB, long long sBias, long long sC)
{
    int bz = blockIdx.z;
    A    += (long long)bz * sA;
    Bm   += (long long)bz * sB;
    bias += (long long)bz * sBias;
    C    += (long long)bz * sC;

    // stride 136 (mod 32 == 8): fragment reads of 4 k-rows x 8 m-cols hit
    // 32 distinct banks -> conflict-free.
    __shared__ uint32_t As[16][136];   // [k][m]
    __shared__ uint32_t Bs[16][136];   // [k][n]

    int t    = threadIdx.x;
    int wid  = t >> 5, lane = t & 31;
    int gid  = lane >> 2, tig = lane & 3;
    int wm0  = (wid & 1) * 64;         // warp m offset in block tile
    int wn0  = (wid >> 1) * 32;        // warp n offset
    int m0   = blockIdx.y * 128, n0 = blockIdx.x * 128;

    float acc[4][4][4];
#pragma unroll
    for (int mt = 0; mt < 4; mt++)
#pragma unroll
        for (int nt = 0; nt < 4; nt++)
#pragma unroll
            for (int r = 0; r < 4; r++) acc[mt][nt][r] = 0.f;

    for (int k0 = 0; k0 < K; k0 += 16) {
        // stage A 128x16 (transposed to [k][m]) with tf32 rounding
#pragma unroll
        for (int l = 0; l < 2; l++) {
            int f  = t + l * 256;
            int r  = f >> 2;
            int c4 = (f & 3) * 4;
            float4 v = *(const float4*)(A + (long long)(m0 + r) * K + k0 + c4);
            As[c4 + 0][r] = f2tf32(v.x);
            As[c4 + 1][r] = f2tf32(v.y);
            As[c4 + 2][r] = f2tf32(v.z);
            As[c4 + 3][r] = f2tf32(v.w);
        }
        // stage B 16x128
#pragma unroll
        for (int l = 0; l < 2; l++) {
            int f  = t + l * 256;
            int r  = f >> 5;
            int c4 = (f & 31) * 4;
            float4 v = *(const float4*)(Bm + (long long)(k0 + r) * Nc + n0 + c4);
            Bs[r][c4 + 0] = f2tf32(v.x);
            Bs[r][c4 + 1] = f2tf32(v.y);
            Bs[r][c4 + 2] = f2tf32(v.z);
            Bs[r][c4 + 3] = f2tf32(v.w);
        }
        __syncthreads();

#pragma unroll
        for (int kb = 0; kb < 16; kb += 8) {
            uint32_t af[4][4], bf[4][2];
#pragma unroll
            for (int mt = 0; mt < 4; mt++) {
                int mm = wm0 + mt * 16 + gid;
                af[mt][0] = As[kb + tig    ][mm];
                af[mt][1] = As[kb + tig    ][mm + 8];
                af[mt][2] = As[kb + tig + 4][mm];
                af[mt][3] = As[kb + tig + 4][mm + 8];
            }
#pragma unroll
            for (int nt = 0; nt < 4; nt++) {
                int nn = wn0 + nt * 8 + gid;
                bf[nt][0] = Bs[kb + tig    ][nn];
                bf[nt][1] = Bs[kb + tig + 4][nn];
            }
#pragma unroll
            for (int mt = 0; mt < 4; mt++)
#pragma unroll
                for (int nt = 0; nt < 4; nt++) {
                    asm volatile(
                        "mma.sync.aligned.m16n8k8.row.col.f32.tf32.tf32.f32 "
                        "{%0,%1,%2,%3}, {%4,%5,%6,%7}, {%8,%9}, {%0,%1,%2,%3};"
                        : "+f"(acc[mt][nt][0]), "+f"(acc[mt][nt][1]),
                          "+f"(acc[mt][nt][2]), "+f"(acc[mt][nt][3])
                        : "r"(af[mt][0]), "r"(af[mt][1]),
                          "r"(af[mt][2]), "r"(af[mt][3]),
                          "r"(bf[nt][0]), "r"(bf[nt][1]));
                }
        }
        __syncthreads();
    }

    // epilogue
#pragma unroll
    for (int mt = 0; mt < 4; mt++) {
#pragma unroll
        for (int nt = 0; nt < 4; nt++) {
            int row = m0 + wm0 + mt * 16 + gid;
            int col = n0 + wn0 + nt * 8 + 2 * tig;
            float b0 = bias[col], b1 = bias[col + 1];
            float c0 = acc[mt][nt][0] + b0;
            float c1 = acc[mt][nt][1] + b1;
            float c2 = acc[mt][nt][2] + b0;
            float c3 = acc[mt][nt][3] + b1;
            if (RELU) {
                c0 = fmaxf(c0, 0.f); c1 = fmaxf(c1, 0.f);
                c2 = fmaxf(c2, 0.f); c3 = fmaxf(c3, 0.f);
            }
            *(float2*)(C + (long long)row * Nc + col)       = make_float2(c0, c1);
            *(float2*)(C + (long long)(row + 8) * Nc + col) = make_float2(c2, c3);
        }
    }
}

// ---------------- flash attention (fp32, causal) ----------------
constexpr int QT = 128, KT = 64;
constexpr int ATTN_SMEM = (QT * (HD + 1) + 2 * KT * HD) * 4;  // 66048 B

__global__ void __launch_bounds__(128) attn_kernel(
    const float* __restrict__ Q, const float* __restrict__ Kg,
    const float* __restrict__ Vg, float* __restrict__ O)
{
    extern __shared__ float sm[];
    float* q_s = sm;                       // [QT][HD+1]
    float* k_s = sm + QT * (HD + 1);       // [KT][HD]
    float* v_s = k_s + KT * HD;            // [KT][HD]

    int bh = blockIdx.y;
    int h  = bh % H, b = bh / H;
    int q0 = blockIdx.x * QT;
    int t  = threadIdx.x;
    long base = (long)b * D + (long)h * HD;

    for (int f = t; f < QT * HD / 4; f += 128) {
        int r  = f / (HD / 4);
        int c4 = (f % (HD / 4)) * 4;
        float4 v = *(const float4*)(Q + (long)(q0 + r) * (B * D) + base + c4);
        q_s[r * (HD + 1) + c4 + 0] = v.x;
        q_s[r * (HD + 1) + c4 + 1] = v.y;
        q_s[r * (HD + 1) + c4 + 2] = v.z;
        q_s[r * (HD + 1) + c4 + 3] = v.w;
    }
    __syncthreads();

    int sq = q0 + t;
    float m_run = -1e30f, l_run = 0.f;
    float acc[HD];
#pragma unroll
    for (int d = 0; d < HD; d++) acc[d] = 0.f;

    int kend = q0 + QT;
    for (int k0 = 0; k0 < kend; k0 += KT) {
        for (int f = t; f < KT * HD / 4; f += 128) {
            int r  = f / (HD / 4);
            int c4 = (f % (HD / 4)) * 4;
            *(float4*)(&k_s[r * HD + c4]) =
                *(const float4*)(Kg + (long)(k0 + r) * (B * D) + base + c4);
            *(float4*)(&v_s[r * HD + c4]) =
                *(const float4*)(Vg + (long)(k0 + r) * (B * D) + base + c4);
        }
        __syncthreads();

        float s[KT];
#pragma unroll
        for (int j = 0; j < KT; j++) s[j] = 0.f;
        for (int d = 0; d < HD; d++) {
            float qd = q_s[t * (HD + 1) + d];
#pragma unroll
            for (int j = 0; j < KT; j++) s[j] += qd * k_s[j * HD + d];
        }
        float mnew = m_run;
#pragma unroll
        for (int j = 0; j < KT; j++) {
            if (k0 + j > sq) s[j] = -1e9f;
            mnew = fmaxf(mnew, s[j]);
        }
        float corr = __expf(m_run - mnew);
        l_run *= corr;
#pragma unroll
        for (int d = 0; d < HD; d++) acc[d] *= corr;
        for (int j = 0; j < KT; j++) {
            float p = __expf(s[j] - mnew);
            l_run += p;
#pragma unroll
            for (int d = 0; d < HD; d++) acc[d] += p * v_s[j * HD + d];
        }
        m_run = mnew;
        __syncthreads();
    }
    float inv = 1.f / l_run;
    float* op = O + (long)sq * (B * D) + base;
#pragma unroll
    for (int c4 = 0; c4 < HD; c4 += 4) {
        float4 v;
        v.x = acc[c4 + 0] * inv; v.y = acc[c4 + 1] * inv;
        v.z = acc[c4 + 2] * inv; v.w = acc[c4 + 3] * inv;
        *(float4*)(op + c4) = v;
    }
}

// ---------------- gate: logits, softmax, argmax (fp32, exact) ----------------
__global__ void __launch_bounds__(256) gate_kernel(
    const float* __restrict__ tok, const float* __restrict__ gw,
    float* __restrict__ gates, int* __restrict__ eidx, float* __restrict__ gp)
{
    int n = blockIdx.x, t = threadIdx.x;
    const float* row = tok + (long)n * D;
    float p[E];
#pragma unroll
    for (int e = 0; e < E; e++) p[e] = 0.f;
    for (int d = t; d < D; d += 256) {
        float xv = row[d];
        const float* w = gw + (long)d * E;
#pragma unroll
        for (int e = 0; e < E; e++) p[e] += xv * w[e];
    }
    __shared__ float red[256 * E];
#pragma unroll
    for (int e = 0; e < E; e++) red[t * E + e] = p[e];
    __syncthreads();
    for (int st = 128; st > 0; st >>= 1) {
        if (t < st)
#pragma unroll
            for (int e = 0; e < E; e++) red[t * E + e] += red[(t + st) * E + e];
        __syncthreads();
    }
    if (t == 0) {
        float lg[E], mx = -1e30f;
#pragma unroll
        for (int e = 0; e < E; e++) { lg[e] = red[e]; mx = fmaxf(mx, lg[e]); }
        float sum = 0.f, pr[E];
#pragma unroll
        for (int e = 0; e < E; e++) { pr[e] = __expf(lg[e] - mx); sum += pr[e]; }
        float inv = 1.f / sum;
        int best = 0; float bv = -1e30f;
#pragma unroll
        for (int e = 0; e < E; e++) {
            float g = pr[e] * inv;
            gates[(long)n * E + e] = g;
            if (g > bv) { bv = g; best = e; }
        }
        eidx[n] = best;
        gp[n]   = bv;
    }
}

// ---------------- routing scan (deterministic, single block) ----------------
__global__ void __launch_bounds__(256) scan_kernel(
    const int* __restrict__ eidx, const float* __restrict__ gp,
    int* __restrict__ slot, float* __restrict__ gv, int* __restrict__ cnt)
{
    __shared__ int scnt[256][E];
    int t = threadIdx.x;
    int c[E];
#pragma unroll
    for (int e = 0; e < E; e++) c[e] = 0;
    int n0 = t * (N / 256);
    for (int i = 0; i < N / 256; i++) c[eidx[n0 + i]]++;
#pragma unroll
    for (int e = 0; e < E; e++) scnt[t][e] = c[e];
    __syncthreads();
    if (t < E) {
        int run = 0;
        for (int j = 0; j < 256; j++) { int tmp = scnt[j][t]; scnt[j][t] = run; run += tmp; }
        cnt[t] = run;
    }
    __syncthreads();
    int off[E];
#pragma unroll
    for (int e = 0; e < E; e++) off[e] = scnt[t][e];
    for (int i = 0; i < N / 256; i++) {
        int n = n0 + i;
        int e = eidx[n];
        int l = off[e]++;
        bool keep = (l < CAP);
        slot[n] = keep ? e * CAP + l : -1;
        gv[n]   = keep ? gp[n] : 0.f;
    }
}

// ---------------- l_aux (deterministic tree reduce) ----------------
__global__ void __launch_bounds__(256) laux_kernel(
    const float* __restrict__ gates, const int* __restrict__ cnt,
    float* __restrict__ out_laux)
{
    __shared__ float red[256];
    int t = threadIdx.x;
    float loc[E];
#pragma unroll
    for (int e = 0; e < E; e++) loc[e] = 0.f;
    for (int n = t; n < N; n += 256)
#pragma unroll
        for (int e = 0; e < E; e++) loc[e] += gates[(long)n * E + e];
    float total[E];
    for (int e = 0; e < E; e++) {
        red[t] = loc[e]; __syncthreads();
        for (int st = 128; st > 0; st >>= 1) {
            if (t < st) red[t] += red[t + st];
            __syncthreads();
        }
        if (t == 0) total[e] = red[0];
        __syncthreads();
    }
    if (t == 0) {
        float la = 0.f;
        for (int e = 0; e < E; e++)
            la += (total[e] / N) * ((float)cnt[e] / N);
        *out_laux = (float)E * la;
    }
}

// ---------------- dispatch / combine ----------------
__global__ void __launch_bounds__(256) dispatch_kernel(
    const float* __restrict__ tok, const int* __restrict__ slot,
    float* __restrict__ disp)
{
    int n = blockIdx.x;
    int s = slot[n];
    if (s < 0) return;
    const float4* src = (const float4*)(tok + (long)n * D);
    float4* dst = (float4*)(disp + (long)s * D);
    dst[threadIdx.x] = src[threadIdx.x];
}

__global__ void __launch_bounds__(256) combine_kernel(
    const float* __restrict__ x1, const float* __restrict__ eo,
    const int* __restrict__ slot, const float* __restrict__ gv,
    float* __restrict__ out)
{
    int n = blockIdx.x, t = threadIdx.x;
    int s = slot[n];
    float g = gv[n];
    float4 r = ((const float4*)(x1 + (long)n * D))[t];
    if (s >= 0) {
        float4 v = ((const float4*)(eo + (long)s * D))[t];
        r.x += v.x * g; r.y += v.y * g; r.z += v.z * g; r.w += v.w * g;
    }
    ((float4*)(out + (long)n * D))[t] = r;
}

// ---------------- launch ----------------
extern "C" void kernel_launch(void* const* d_in, const int* in_sizes, int n_in,
                              void* d_out, int out_size) {
    const float* x    = (const float*)d_in[0];
    const float* wq   = (const float*)d_in[2];
    const float* bq   = (const float*)d_in[3];
    const float* wk   = (const float*)d_in[4];
    const float* bk   = (const float*)d_in[5];
    const float* wv   = (const float*)d_in[6];
    const float* bv   = (const float*)d_in[7];
    const float* wo   = (const float*)d_in[8];
    const float* bo   = (const float*)d_in[9];
    const float* ln1g = (const float*)d_in[10];
    const float* ln1b = (const float*)d_in[11];
    const float* ln2g = (const float*)d_in[12];
    const float* ln2b = (const float*)d_in[13];
    const float* gw   = (const float*)d_in[14];
    const float* w1   = (const float*)d_in[15];
    const float* b1   = (const float*)d_in[16];
    const float* w2   = (const float*)d_in[17];
    const float* b2   = (const float*)d_in[18];
    float* out = (float*)d_out;

    float *xn, *q, *k, *v, *ao, *x1, *tok, *disp, *hbuf, *eo, *gates, *gp, *gv;
    int *eidx, *slot, *cnt;
    cudaGetSymbolAddress((void**)&xn,   g_xn);
    cudaGetSymbolAddress((void**)&q,    g_q);
    cudaGetSymbolAddress((void**)&k,    g_k);
    cudaGetSymbolAddress((void**)&v,    g_v);
    cudaGetSymbolAddress((void**)&ao,   g_ao);
    cudaGetSymbolAddress((void**)&x1,   g_x1);
    cudaGetSymbolAddress((void**)&tok,  g_tok);
    cudaGetSymbolAddress((void**)&disp, g_disp);
    cudaGetSymbolAddress((void**)&hbuf, g_h);
    cudaGetSymbolAddress((void**)&eo,   g_eo);
    cudaGetSymbolAddress((void**)&gates,g_gates);
    cudaGetSymbolAddress((void**)&gp,   g_gp);
    cudaGetSymbolAddress((void**)&gv,   g_gv);
    cudaGetSymbolAddress((void**)&eidx, g_eidx);
    cudaGetSymbolAddress((void**)&slot, g_slot);
    cudaGetSymbolAddress((void**)&cnt,  g_cnt);

    cudaFuncSetAttribute(attn_kernel,
                         cudaFuncAttributeMaxDynamicSharedMemorySize, ATTN_SMEM);

    const float qscale = 0.125f;  // HD^-0.5

    // 1) LN1
    ln_kernel<<<N, 256>>>(x, ln1g, ln1b, xn);
    // 2) Q/K/V projections (fp32: upstream of routing decisions)
    gemm_kernel<<<dim3(D / 128, N / 128, 1), 256>>>(xn, wq, bq, nullptr, q,
        N, D, D, qscale, 0, 0, 0, 0, 0);
    gemm_kernel<<<dim3(D / 128, N / 128, 1), 256>>>(xn, wk, bk, nullptr, k,
        N, D, D, 1.f, 0, 0, 0, 0, 0);
    gemm_kernel<<<dim3(D / 128, N / 128, 1), 256>>>(xn, wv, bv, nullptr, v,
        N, D, D, 1.f, 0, 0, 0, 0, 0);
    // 3) attention
    attn_kernel<<<dim3(S / QT, B * H), 128, ATTN_SMEM>>>(q, k, v, ao);
    // 4) output projection + residual (fp32)
    gemm_kernel<<<dim3(D / 128, N / 128, 1), 256>>>(ao, wo, bo, x, x1,
        N, D, D, 1.f, 0, 0, 0, 0, 0);
    // 5) LN2
    ln_kernel<<<N, 256>>>(x1, ln2g, ln2b, tok);
    // 6) gate (fp32, exact argmax)
    gate_kernel<<<N, 256>>>(tok, gw, gates, eidx, gp);
    // 7) routing scan
    scan_kernel<<<1, 256>>>(eidx, gp, slot, gv, cnt);
    // 8) l_aux -> last output element
    laux_kernel<<<1, 256>>>(gates, cnt, out + (out_size - 1));
    // 9) dispatch
    dispatch_kernel<<<N, 256>>>(tok, slot, disp);
    // 10) expert GEMM1 (relu) — tf32 tensor cores
    gemm_tf32_kernel<1><<<dim3(F / 128, CAP / 128, E), 256>>>(disp, w1, b1, hbuf,
        CAP, F, D,
        (long long)CAP * D, (long long)D * F, (long long)F, (long long)CAP * F);
    // 11) expert GEMM2 — tf32 tensor cores
    gemm_tf32_kernel<0><<<dim3(D / 128, CAP / 128, E), 256>>>(hbuf, w2, b2, eo,
        CAP, D, F,
        (long long)CAP * F, (long long)F * D, (long long)D, (long long)CAP * D);
    // 12) combine + residual -> output
    combine_kernel<<<N, 256>>>(x1, eo, slot, gv, out);
}

// round 3
// speedup vs baseline: 2.4869x; 1.2789x over previous
#include <cuda_runtime.h>
#include <cstdint>

// ---------------- problem constants ----------------
constexpr int S = 1024, B = 8, D = 1024, H = 16, F = 4096, E = 8;
constexpr int HD = D / H;           // 64
constexpr int N = S * B;            // 8192
constexpr int CAP = 4 * N / E;      // 4096

// ---------------- scratch (device globals; no allocations) ----------------
__device__ float g_xn [N * D];
__device__ float g_q  [N * D];
__device__ float g_k  [N * D];
__device__ float g_v  [N * D];
__device__ float g_ao [N * D];
__device__ float g_x1 [N * D];
__device__ float g_tok[N * D];
__device__ uint16_t g_dispb[E * CAP * D];            // bf16 dispatched tokens
__device__ uint16_t g_hb  [134217728];               // E*CAP*F bf16 hidden
__device__ float    g_eo  [E * CAP * D];
__device__ uint32_t g_w1p [(D / 2) * F * E];         // bf16 k-pair packed w1
__device__ uint32_t g_w2p [(F / 2) * D * E];         // bf16 k-pair packed w2
__device__ float g_gates[N * E];
__device__ int   g_eidx[N];
__device__ float g_gp  [N];
__device__ int   g_slot[N];
__device__ float g_gv  [N];
__device__ int   g_cnt [E];

// ---------------- helpers ----------------
__device__ __forceinline__ uint32_t f2tf32(float f) {
    uint32_t u;
    asm("cvt.rna.tf32.f32 %0, %1;" : "=r"(u) : "f"(f));
    return u;
}
// pack two fp32 into bf16x2: element order (lo = first, hi = second)
__device__ __forceinline__ uint32_t packbf2(float lo, float hi) {
    uint32_t d;
    asm("cvt.rn.bf16x2.f32 %0, %1, %2;" : "=r"(d) : "f"(hi), "f"(lo));
    return d;
}

// ---------------- LayerNorm ----------------
__global__ void __launch_bounds__(256) ln_kernel(const float* __restrict__ x,
                                                 const float* __restrict__ gam,
                                                 const float* __restrict__ bet,
                                                 float* __restrict__ y) {
    int n = blockIdx.x;
    const float* row = x + (long)n * D;
    int t = threadIdx.x;
    float s = 0.f, s2 = 0.f;
    for (int d = t; d < D; d += 256) { float v = row[d]; s += v; s2 += v * v; }
    __shared__ float r1[256], r2[256];
    r1[t] = s; r2[t] = s2; __syncthreads();
    for (int st = 128; st > 0; st >>= 1) {
        if (t < st) { r1[t] += r1[t + st]; r2[t] += r2[t + st]; }
        __syncthreads();
    }
    float mean = r1[0] / D;
    float var  = r2[0] / D - mean * mean;
    float inv  = rsqrtf(var + 1e-5f);
    float* yo = y + (long)n * D;
    for (int d = t; d < D; d += 256)
        yo[d] = (row[d] - mean) * inv * gam[d] + bet[d];
}

// ---------------- 3xTF32 tensor GEMM (projections; near-fp32 accuracy) ------
// C[M,Nc] = (A @ Bm + bias) * scale (+ resid). Block 128x128, warp 64x32.
template<int HAS_RESID>
__global__ void __launch_bounds__(256) gemm_tf32x3_kernel(
    const float* __restrict__ A, const float* __restrict__ Bm,
    const float* __restrict__ bias, const float* __restrict__ resid,
    float* __restrict__ C, int M, int Nc, int K, float scale)
{
    __shared__ uint32_t As_h[16][136], As_l[16][136];
    __shared__ uint32_t Bs_h[16][136], Bs_l[16][136];

    int t    = threadIdx.x;
    int wid  = t >> 5, lane = t & 31;
    int gid  = lane >> 2, tig = lane & 3;
    int wm0  = (wid & 1) * 64;
    int wn0  = (wid >> 1) * 32;
    int m0   = blockIdx.y * 128, n0 = blockIdx.x * 128;

    float acc[4][4][4];
#pragma unroll
    for (int mt = 0; mt < 4; mt++)
#pragma unroll
        for (int nt = 0; nt < 4; nt++)
#pragma unroll
            for (int r = 0; r < 4; r++) acc[mt][nt][r] = 0.f;

    for (int k0 = 0; k0 < K; k0 += 16) {
#pragma unroll
        for (int l = 0; l < 2; l++) {
            int f  = t + l * 256;
            int r  = f >> 2;
            int c4 = (f & 3) * 4;
            float4 v = *(const float4*)(A + (long long)(m0 + r) * K + k0 + c4);
            float vv[4] = {v.x, v.y, v.z, v.w};
#pragma unroll
            for (int j = 0; j < 4; j++) {
                uint32_t hb = f2tf32(vv[j]);
                float lo = vv[j] - __uint_as_float(hb);
                As_h[c4 + j][r] = hb;
                As_l[c4 + j][r] = f2tf32(lo);
            }
        }
#pragma unroll
        for (int l = 0; l < 2; l++) {
            int f  = t + l * 256;
            int r  = f >> 5;
            int c4 = (f & 31) * 4;
            float4 v = *(const float4*)(Bm + (long long)(k0 + r) * Nc + n0 + c4);
            float vv[4] = {v.x, v.y, v.z, v.w};
#pragma unroll
            for (int j = 0; j < 4; j++) {
                uint32_t hb = f2tf32(vv[j]);
                float lo = vv[j] - __uint_as_float(hb);
                Bs_h[r][c4 + j] = hb;
                Bs_l[r][c4 + j] = f2tf32(lo);
            }
        }
        __syncthreads();

#pragma unroll
        for (int kb = 0; kb < 16; kb += 8) {
            uint32_t ah[4][4], al[4][4], bh[4][2], bl[4][2];
#pragma unroll
            for (int mt = 0; mt < 4; mt++) {
                int mm = wm0 + mt * 16 + gid;
                ah[mt][0] = As_h[kb + tig    ][mm];
                ah[mt][1] = As_h[kb + tig    ][mm + 8];
                ah[mt][2] = As_h[kb + tig + 4][mm];
                ah[mt][3] = As_h[kb + tig + 4][mm + 8];
                al[mt][0] = As_l[kb + tig    ][mm];
                al[mt][1] = As_l[kb + tig    ][mm + 8];
                al[mt][2] = As_l[kb + tig + 4][mm];
                al[mt][3] = As_l[kb + tig + 4][mm + 8];
            }
#pragma unroll
            for (int nt = 0; nt < 4; nt++) {
                int nn = wn0 + nt * 8 + gid;
                bh[nt][0] = Bs_h[kb + tig    ][nn];
                bh[nt][1] = Bs_h[kb + tig + 4][nn];
                bl[nt][0] = Bs_l[kb + tig    ][nn];
                bl[nt][1] = Bs_l[kb + tig + 4][nn];
            }
#pragma unroll
            for (int mt = 0; mt < 4; mt++)
#pragma unroll
                for (int nt = 0; nt < 4; nt++) {
                    asm volatile(
                        "mma.sync.aligned.m16n8k8.row.col.f32.tf32.tf32.f32 "
                        "{%0,%1,%2,%3}, {%4,%5,%6,%7}, {%8,%9}, {%0,%1,%2,%3};"
                        : "+f"(acc[mt][nt][0]), "+f"(acc[mt][nt][1]),
                          "+f"(acc[mt][nt][2]), "+f"(acc[mt][nt][3])
                        : "r"(ah[mt][0]), "r"(ah[mt][1]), "r"(ah[mt][2]), "r"(ah[mt][3]),
                          "r"(bl[nt][0]), "r"(bl[nt][1]));
                    asm volatile(
                        "mma.sync.aligned.m16n8k8.row.col.f32.tf32.tf32.f32 "
                        "{%0,%1,%2,%3}, {%4,%5,%6,%7}, {%8,%9}, {%0,%1,%2,%3};"
                        : "+f"(acc[mt][nt][0]), "+f"(acc[mt][nt][1]),
                          "+f"(acc[mt][nt][2]), "+f"(acc[mt][nt][3])
                        : "r"(al[mt][0]), "r"(al[mt][1]), "r"(al[mt][2]), "r"(al[mt][3]),
                          "r"(bh[nt][0]), "r"(bh[nt][1]));
                    asm volatile(
                        "mma.sync.aligned.m16n8k8.row.col.f32.tf32.tf32.f32 "
                        "{%0,%1,%2,%3}, {%4,%5,%6,%7}, {%8,%9}, {%0,%1,%2,%3};"
                        : "+f"(acc[mt][nt][0]), "+f"(acc[mt][nt][1]),
                          "+f"(acc[mt][nt][2]), "+f"(acc[mt][nt][3])
                        : "r"(ah[mt][0]), "r"(ah[mt][1]), "r"(ah[mt][2]), "r"(ah[mt][3]),
                          "r"(bh[nt][0]), "r"(bh[nt][1]));
                }
        }
        __syncthreads();
    }

#pragma unroll
    for (int mt = 0; mt < 4; mt++) {
#pragma unroll
        for (int nt = 0; nt < 4; nt++) {
            int row = m0 + wm0 + mt * 16 + gid;
            int col = n0 + wn0 + nt * 8 + 2 * tig;
            float b0 = bias[col], b1 = bias[col + 1];
            float c0 = (acc[mt][nt][0] + b0) * scale;
            float c1 = (acc[mt][nt][1] + b1) * scale;
            float c2 = (acc[mt][nt][2] + b0) * scale;
            float c3 = (acc[mt][nt][3] + b1) * scale;
            if (HAS_RESID) {
                float2 r0 = *(const float2*)(resid + (long long)row * Nc + col);
                float2 r1 = *(const float2*)(resid + (long long)(row + 8) * Nc + col);
                c0 += r0.x; c1 += r0.y; c2 += r1.x; c3 += r1.y;
            }
            *(float2*)(C + (long long)row * Nc + col)       = make_float2(c0, c1);
            *(float2*)(C + (long long)(row + 8) * Nc + col) = make_float2(c2, c3);
        }
    }
}

// ---------------- weight packing: fp32 [K][Nc] -> bf16 k-pair u32 [K/2][Nc] --
__global__ void __launch_bounds__(256) packw_kernel(
    const float* __restrict__ W, uint32_t* __restrict__ P, int Nc,
    long long sW, long long sP)
{
    int n  = blockIdx.x * 256 + threadIdx.x;
    int k2 = blockIdx.y;
    int z  = blockIdx.z;
    const float* w = W + (long long)z * sW + (long long)(2 * k2) * Nc + n;
    P[(long long)z * sP + (long long)k2 * Nc + n] = packbf2(w[0], w[Nc]);
}

// ---------------- bf16 tensor GEMM (experts; double-buffered) ---------------
// C = op(A[M,K](bf16) @ Bp(packed bf16 pairs [K/2][Nc]) + bias)
template<int RELU, int OUTBF>
__global__ void __launch_bounds__(256) gemm_bf16_kernel(
    const uint16_t* __restrict__ A, const uint32_t* __restrict__ Bp,
    const float* __restrict__ bias, void* __restrict__ Cout,
    int M, int Nc, int K,
    long long sA, long long sB, long long sBias, long long sC)
{
    __shared__ uint32_t As2[2][8][136];
    __shared__ uint32_t Bs2[2][8][136];

    int z = blockIdx.z;
    A    += (long long)z * sA;
    Bp   += (long long)z * sB;
    bias += (long long)z * sBias;

    int t    = threadIdx.x;
    int wid  = t >> 5, lane = t & 31;
    int gid  = lane >> 2, tig = lane & 3;
    int wm0  = (wid & 1) * 64;
    int wn0  = (wid >> 1) * 32;
    int m0   = blockIdx.y * 128, n0 = blockIdx.x * 128;

    int am = t & 127, ah = t >> 7;          // A staging: row am, k-half ah
    int bk2 = t >> 5, bn = (t & 31) * 4;    // B staging: pair-row bk2, 4 cols

    float acc[4][4][4];
#pragma unroll
    for (int mt = 0; mt < 4; mt++)
#pragma unroll
        for (int nt = 0; nt < 4; nt++)
#pragma unroll
            for (int r = 0; r < 4; r++) acc[mt][nt][r] = 0.f;

    const int nIter = K / 16;
    {   // stage tile 0
        uint4 va = *(const uint4*)(A + (long long)(m0 + am) * K + ah * 8);
        As2[0][ah * 4 + 0][am] = va.x; As2[0][ah * 4 + 1][am] = va.y;
        As2[0][ah * 4 + 2][am] = va.z; As2[0][ah * 4 + 3][am] = va.w;
        uint4 vb = *(const uint4*)(Bp + (long long)bk2 * Nc + n0 + bn);
        *(uint4*)&Bs2[0][bk2][bn] = vb;
    }
    __syncthreads();

    int cur = 0;
    for (int it = 0; it < nIter; ++it) {
        uint4 va, vb;
        bool pf = (it + 1 < nIter);
        if (pf) {
            va = *(const uint4*)(A + (long long)(m0 + am) * K + (it + 1) * 16 + ah * 8);
            vb = *(const uint4*)(Bp + (long long)((it + 1) * 8 + bk2) * Nc + n0 + bn);
        }
        uint32_t af[4][4], bfr[4][2];
#pragma unroll
        for (int mt = 0; mt < 4; mt++) {
            int mm = wm0 + mt * 16 + gid;
            af[mt][0] = As2[cur][tig    ][mm];
            af[mt][1] = As2[cur][tig    ][mm + 8];
            af[mt][2] = As2[cur][tig + 4][mm];
            af[mt][3] = As2[cur][tig + 4][mm + 8];
        }
#pragma unroll
        for (int nt = 0; nt < 4; nt++) {
            int nn = wn0 + nt * 8 + gid;
            bfr[nt][0] = Bs2[cur][tig    ][nn];
            bfr[nt][1] = Bs2[cur][tig + 4][nn];
        }
#pragma unroll
        for (int mt = 0; mt < 4; mt++)
#pragma unroll
            for (int nt = 0; nt < 4; nt++) {
                asm volatile(
                    "mma.sync.aligned.m16n8k16.row.col.f32.bf16.bf16.f32 "
                    "{%0,%1,%2,%3}, {%4,%5,%6,%7}, {%8,%9}, {%0,%1,%2,%3};"
                    : "+f"(acc[mt][nt][0]), "+f"(acc[mt][nt][1]),
                      "+f"(acc[mt][nt][2]), "+f"(acc[mt][nt][3])
                    : "r"(af[mt][0]), "r"(af[mt][1]),
                      "r"(af[mt][2]), "r"(af[mt][3]),
                      "r"(bfr[nt][0]), "r"(bfr[nt][1]));
            }
        if (pf) {
            int nx = cur ^ 1;
            As2[nx][ah * 4 + 0][am] = va.x; As2[nx][ah * 4 + 1][am] = va.y;
            As2[nx][ah * 4 + 2][am] = va.z; As2[nx][ah * 4 + 3][am] = va.w;
            *(uint4*)&Bs2[nx][bk2][bn] = vb;
        }
        __syncthreads();
        cur ^= 1;
    }

#pragma unroll
    for (int mt = 0; mt < 4; mt++) {
#pragma unroll
        for (int nt = 0; nt < 4; nt++) {
            int row = m0 + wm0 + mt * 16 + gid;
            int col = n0 + wn0 + nt * 8 + 2 * tig;
            float b0 = bias[col], b1 = bias[col + 1];
            float c0 = acc[mt][nt][0] + b0;
            float c1 = acc[mt][nt][1] + b1;
            float c2 = acc[mt][nt][2] + b0;
            float c3 = acc[mt][nt][3] + b1;
            if (RELU) {
                c0 = fmaxf(c0, 0.f); c1 = fmaxf(c1, 0.f);
                c2 = fmaxf(c2, 0.f); c3 = fmaxf(c3, 0.f);
            }
            if (OUTBF) {
                uint16_t* Cb = (uint16_t*)Cout + (long long)z * sC;
                *(uint32_t*)(Cb + (long long)row * Nc + col)       = packbf2(c0, c1);
                *(uint32_t*)(Cb + (long long)(row + 8) * Nc + col) = packbf2(c2, c3);
            } else {
                float* Cf = (float*)Cout + (long long)z * sC;
                *(float2*)(Cf + (long long)row * Nc + col)       = make_float2(c0, c1);
                *(float2*)(Cf + (long long)(row + 8) * Nc + col) = make_float2(c2, c3);
            }
        }
    }
}

// ---------------- flash attention (fp32, causal) ----------------
constexpr int QT = 128, KT = 64;
constexpr int ATTN_SMEM = (QT * (HD + 1) + 2 * KT * HD) * 4;  // 66048 B

__global__ void __launch_bounds__(128) attn_kernel(
    const float* __restrict__ Q, const float* __restrict__ Kg,
    const float* __restrict__ Vg, float* __restrict__ O)
{
    extern __shared__ float sm[];
    float* q_s = sm;                       // [QT][HD+1]
    float* k_s = sm + QT * (HD + 1);       // [KT][HD]
    float* v_s = k_s + KT * HD;            // [KT][HD]

    int bh = blockIdx.y;
    int h  = bh % H, b = bh / H;
    int q0 = blockIdx.x * QT;
    int t  = threadIdx.x;
    long base = (long)b * D + (long)h * HD;

    for (int f = t; f < QT * HD / 4; f += 128) {
        int r  = f / (HD / 4);
        int c4 = (f % (HD / 4)) * 4;
        float4 v = *(const float4*)(Q + (long)(q0 + r) * (B * D) + base + c4);
        q_s[r * (HD + 1) + c4 + 0] = v.x;
        q_s[r * (HD + 1) + c4 + 1] = v.y;
        q_s[r * (HD + 1) + c4 + 2] = v.z;
        q_s[r * (HD + 1) + c4 + 3] = v.w;
    }
    __syncthreads();

    int sq = q0 + t;
    float m_run = -1e30f, l_run = 0.f;
    float acc[HD];
#pragma unroll
    for (int d = 0; d < HD; d++) acc[d] = 0.f;

    int kend = q0 + QT;
    for (int k0 = 0; k0 < kend; k0 += KT) {
        for (int f = t; f < KT * HD / 4; f += 128) {
            int r  = f / (HD / 4);
            int c4 = (f % (HD / 4)) * 4;
            *(float4*)(&k_s[r * HD + c4]) =
                *(const float4*)(Kg + (long)(k0 + r) * (B * D) + base + c4);
            *(float4*)(&v_s[r * HD + c4]) =
                *(const float4*)(Vg + (long)(k0 + r) * (B * D) + base + c4);
        }
        __syncthreads();

        float s[KT];
#pragma unroll
        for (int j = 0; j < KT; j++) s[j] = 0.f;
        for (int d = 0; d < HD; d++) {
            float qd = q_s[t * (HD + 1) + d];
#pragma unroll
            for (int j = 0; j < KT; j++) s[j] += qd * k_s[j * HD + d];
        }
        float mnew = m_run;
#pragma unroll
        for (int j = 0; j < KT; j++) {
            if (k0 + j > sq) s[j] = -1e9f;
            mnew = fmaxf(mnew, s[j]);
        }
        float corr = __expf(m_run - mnew);
        l_run *= corr;
#pragma unroll
        for (int d = 0; d < HD; d++) acc[d] *= corr;
        for (int j = 0; j < KT; j++) {
            float p = __expf(s[j] - mnew);
            l_run += p;
#pragma unroll
            for (int d = 0; d < HD; d++) acc[d] += p * v_s[j * HD + d];
        }
        m_run = mnew;
        __syncthreads();
    }
    float inv = 1.f / l_run;
    float* op = O + (long)sq * (B * D) + base;
#pragma unroll
    for (int c4 = 0; c4 < HD; c4 += 4) {
        float4 v;
        v.x = acc[c4 + 0] * inv; v.y = acc[c4 + 1] * inv;
        v.z = acc[c4 + 2] * inv; v.w = acc[c4 + 3] * inv;
        *(float4*)(op + c4) = v;
    }
}

// ---------------- gate: logits, softmax, argmax (fp32, exact) ----------------
__global__ void __launch_bounds__(256) gate_kernel(
    const float* __restrict__ tok, const float* __restrict__ gw,
    float* __restrict__ gates, int* __restrict__ eidx, float* __restrict__ gp)
{
    int n = blockIdx.x, t = threadIdx.x;
    const float* row = tok + (long)n * D;
    float p[E];
#pragma unroll
    for (int e = 0; e < E; e++) p[e] = 0.f;
    for (int d = t; d < D; d += 256) {
        float xv = row[d];
        const float* w = gw + (long)d * E;
#pragma unroll
        for (int e = 0; e < E; e++) p[e] += xv * w[e];
    }
    __shared__ float red[256 * E];
#pragma unroll
    for (int e = 0; e < E; e++) red[t * E + e] = p[e];
    __syncthreads();
    for (int st = 128; st > 0; st >>= 1) {
        if (t < st)
#pragma unroll
            for (int e = 0; e < E; e++) red[t * E + e] += red[(t + st) * E + e];
        __syncthreads();
    }
    if (t == 0) {
        float lg[E], mx = -1e30f;
#pragma unroll
        for (int e = 0; e < E; e++) { lg[e] = red[e]; mx = fmaxf(mx, lg[e]); }
        float sum = 0.f, pr[E];
#pragma unroll
        for (int e = 0; e < E; e++) { pr[e] = __expf(lg[e] - mx); sum += pr[e]; }
        float inv = 1.f / sum;
        int best = 0; float bv = -1e30f;
#pragma unroll
        for (int e = 0; e < E; e++) {
            float g = pr[e] * inv;
            gates[(long)n * E + e] = g;
            if (g > bv) { bv = g; best = e; }
        }
        eidx[n] = best;
        gp[n]   = bv;
    }
}

// ---------------- routing scan (deterministic, single block) ----------------
__global__ void __launch_bounds__(256) scan_kernel(
    const int* __restrict__ eidx, const float* __restrict__ gp,
    int* __restrict__ slot, float* __restrict__ gv, int* __restrict__ cnt)
{
    __shared__ int scnt[256][E];
    int t = threadIdx.x;
    int c[E];
#pragma unroll
    for (int e = 0; e < E; e++) c[e] = 0;
    int n0 = t * (N / 256);
    for (int i = 0; i < N / 256; i++) c[eidx[n0 + i]]++;
#pragma unroll
    for (int e = 0; e < E; e++) scnt[t][e] = c[e];
    __syncthreads();
    if (t < E) {
        int run = 0;
        for (int j = 0; j < 256; j++) { int tmp = scnt[j][t]; scnt[j][t] = run; run += tmp; }
        cnt[t] = run;
    }
    __syncthreads();
    int off[E];
#pragma unroll
    for (int e = 0; e < E; e++) off[e] = scnt[t][e];
    for (int i = 0; i < N / 256; i++) {
        int n = n0 + i;
        int e = eidx[n];
        int l = off[e]++;
        bool keep = (l < CAP);
        slot[n] = keep ? e * CAP + l : -1;
        gv[n]   = keep ? gp[n] : 0.f;
    }
}

// ---------------- l_aux (deterministic tree reduce) ----------------
__global__ void __launch_bounds__(256) laux_kernel(
    const float* __restrict__ gates, const int* __restrict__ cnt,
    float* __restrict__ out_laux)
{
    __shared__ float red[256];
    int t = threadIdx.x;
    float loc[E];
#pragma unroll
    for (int e = 0; e < E; e++) loc[e] = 0.f;
    for (int n = t; n < N; n += 256)
#pragma unroll
        for (int e = 0; e < E; e++) loc[e] += gates[(long)n * E + e];
    float total[E];
    for (int e = 0; e < E; e++) {
        red[t] = loc[e]; __syncthreads();
        for (int st = 128; st > 0; st >>= 1) {
            if (t < st) red[t] += red[t + st];
            __syncthreads();
        }
        if (t == 0) total[e] = red[0];
        __syncthreads();
    }
    if (t == 0) {
        float la = 0.f;
        for (int e = 0; e < E; e++)
            la += (total[e] / N) * ((float)cnt[e] / N);
        *out_laux = (float)E * la;
    }
}

// ---------------- dispatch (fp32 tok -> bf16 slot row) / combine ------------
__global__ void __launch_bounds__(256) dispatch_kernel(
    const float* __restrict__ tok, const int* __restrict__ slot,
    uint16_t* __restrict__ dispb)
{
    int n = blockIdx.x;
    int s = slot[n];
    if (s < 0) return;
    int t = threadIdx.x;
    float4 v = ((const float4*)(tok + (long)n * D))[t];
    uint2 o;
    o.x = packbf2(v.x, v.y);
    o.y = packbf2(v.z, v.w);
    *(uint2*)(dispb + (long)s * D + t * 4) = o;
}

__global__ void __launch_bounds__(256) combine_kernel(
    const float* __restrict__ x1, const float* __restrict__ eo,
    const int* __restrict__ slot, const float* __restrict__ gv,
    float* __restrict__ out)
{
    int n = blockIdx.x, t = threadIdx.x;
    int s = slot[n];
    float g = gv[n];
    float4 r = ((const float4*)(x1 + (long)n * D))[t];
    if (s >= 0) {
        float4 v = ((const float4*)(eo + (long)s * D))[t];
        r.x += v.x * g; r.y += v.y * g; r.z += v.z * g; r.w += v.w * g;
    }
    ((float4*)(out + (long)n * D))[t] = r;
}

// ---------------- launch ----------------
extern "C" void kernel_launch(void* const* d_in, const int* in_sizes, int n_in,
                              void* d_out, int out_size) {
    const float* x    = (const float*)d_in[0];
    const float* wq   = (const float*)d_in[2];
    const float* bq   = (const float*)d_in[3];
    const float* wk   = (const float*)d_in[4];
    const float* bk   = (const float*)d_in[5];
    const float* wv   = (const float*)d_in[6];
    const float* bv   = (const float*)d_in[7];
    const float* wo   = (const float*)d_in[8];
    const float* bo   = (const float*)d_in[9];
    const float* ln1g = (const float*)d_in[10];
    const float* ln1b = (const float*)d_in[11];
    const float* ln2g = (const float*)d_in[12];
    const float* ln2b = (const float*)d_in[13];
    const float* gw   = (const float*)d_in[14];
    const float* w1   = (const float*)d_in[15];
    const float* b1   = (const float*)d_in[16];
    const float* w2   = (const float*)d_in[17];
    const float* b2   = (const float*)d_in[18];
    float* out = (float*)d_out;

    float *xn, *q, *k, *v, *ao, *x1, *tok, *eo, *gates, *gp, *gv;
    uint16_t *dispb, *hb;
    uint32_t *w1p, *w2p;
    int *eidx, *slot, *cnt;
    cudaGetSymbolAddress((void**)&xn,    g_xn);
    cudaGetSymbolAddress((void**)&q,     g_q);
    cudaGetSymbolAddress((void**)&k,     g_k);
    cudaGetSymbolAddress((void**)&v,     g_v);
    cudaGetSymbolAddress((void**)&ao,    g_ao);
    cudaGetSymbolAddress((void**)&x1,    g_x1);
    cudaGetSymbolAddress((void**)&tok,   g_tok);
    cudaGetSymbolAddress((void**)&dispb, g_dispb);
    cudaGetSymbolAddress((void**)&hb,    g_hb);
    cudaGetSymbolAddress((void**)&eo,    g_eo);
    cudaGetSymbolAddress((void**)&w1p,   g_w1p);
    cudaGetSymbolAddress((void**)&w2p,   g_w2p);
    cudaGetSymbolAddress((void**)&gates, g_gates);
    cudaGetSymbolAddress((void**)&gp,    g_gp);
    cudaGetSymbolAddress((void**)&gv,    g_gv);
    cudaGetSymbolAddress((void**)&eidx,  g_eidx);
    cudaGetSymbolAddress((void**)&slot,  g_slot);
    cudaGetSymbolAddress((void**)&cnt,   g_cnt);

    cudaFuncSetAttribute(attn_kernel,
                         cudaFuncAttributeMaxDynamicSharedMemorySize, ATTN_SMEM);

    const float qscale = 0.125f;  // HD^-0.5

    // weight packing for expert GEMMs (independent; do first)
    packw_kernel<<<dim3(F / 256, D / 2, E), 256>>>(w1, w1p, F,
        (long long)D * F, (long long)(D / 2) * F);
    packw_kernel<<<dim3(D / 256, F / 2, E), 256>>>(w2, w2p, D,
        (long long)F * D, (long long)(F / 2) * D);

    // 1) LN1
    ln_kernel<<<N, 256>>>(x, ln1g, ln1b, xn);
    // 2) Q/K/V projections (3xTF32: near-fp32, routing-safe)
    gemm_tf32x3_kernel<0><<<dim3(D / 128, N / 128), 256>>>(xn, wq, bq, nullptr, q,
        N, D, D, qscale);
    gemm_tf32x3_kernel<0><<<dim3(D / 128, N / 128), 256>>>(xn, wk, bk, nullptr, k,
        N, D, D, 1.f);
    gemm_tf32x3_kernel<0><<<dim3(D / 128, N / 128), 256>>>(xn, wv, bv, nullptr, v,
        N, D, D, 1.f);
    // 3) attention (fp32)
    attn_kernel<<<dim3(S / QT, B * H), 128, ATTN_SMEM>>>(q, k, v, ao);
    // 4) output projection + residual (3xTF32)
    gemm_tf32x3_kernel<1><<<dim3(D / 128, N / 128), 256>>>(ao, wo, bo, x, x1,
        N, D, D, 1.f);
    // 5) LN2
    ln_kernel<<<N, 256>>>(x1, ln2g, ln2b, tok);
    // 6) gate (fp32, exact argmax)
    gate_kernel<<<N, 256>>>(tok, gw, gates, eidx, gp);
    // 7) routing scan
    scan_kernel<<<1, 256>>>(eidx, gp, slot, gv, cnt);
    // 8) l_aux -> last output element
    laux_kernel<<<1, 256>>>(gates, cnt, out + (out_size - 1));
    // 9) dispatch (writes bf16)
    dispatch_kernel<<<N, 256>>>(tok, slot, dispb);
    // 10) expert GEMM1 (relu, bf16 in, bf16 out)
    gemm_bf16_kernel<1, 1><<<dim3(F / 128, CAP / 128, E), 256>>>(
        dispb, w1p, b1, hb, CAP, F, D,
        (long long)CAP * D, (long long)(D / 2) * F, (long long)F, (long long)CAP * F);
    // 11) expert GEMM2 (bf16 in, fp32 out)
    gemm_bf16_kernel<0, 0><<<dim3(D / 128, CAP / 128, E), 256>>>(
        hb, w2p, b2, eo, CAP, D, F,
        (long long)CAP * F, (long long)(F / 2) * D, (long long)D, (long long)CAP * D);
    // 12) combine + residual -> output
    combine_kernel<<<N, 256>>>(x1, eo, slot, gv, out);
}